// round 15
// baseline (speedup 1.0000x reference)
#include <cuda_runtime.h>
#include <cstdint>
#include <cstddef>

#define N_NODES 20000
#define N_EDGES 320000
#define EPB 16

#define LOG2_C       0.6931471805599453f
#define INV_SQRT3_C  0.5773502691896258f
#define INV_SQRT8_C  0.35355339059327373f
#define W_SCALE      0.125f
#define INV_MUL_C    0.125f
#define SC_A_C       0.02209708691207961f   // 1/sqrt(128) * 1/sqrt(16)
#define SC_B_C       0.04419417382415922f   // 1/sqrt(512)

#define ROWS_S 20032
#define ROWS_V 60032
#define TILES_S 313
#define TILES_V 938

// scratch (__device__ globals). Referenced ONLY from device code.
__device__ __align__(1024) float d_sv[(size_t)N_NODES * 256];
__device__ __align__(1024) float d_cat_s[(size_t)ROWS_S * 640];
__device__ __align__(1024) float d_cat_v[(size_t)ROWS_V * 640];
__device__ __align__(1024) float d_WcatT_s[64 * 640];
__device__ __align__(1024) float d_WcatT_v[64 * 640];
__device__ __align__(1024) int   d_cnt[N_NODES];
__device__ __align__(1024) int   d_ofs[N_NODES];
__device__ __align__(1024) int   d_perm[N_EDGES];

__device__ __forceinline__ unsigned smem_u32(const void* p) {
    return (unsigned)__cvta_generic_to_shared(p);
}
__device__ __forceinline__ float4 ld4s(const float* p) {
    return *reinterpret_cast<const float4*>(p);
}
__device__ __forceinline__ void cp_async16(unsigned saddr, const void* gaddr) {
    asm volatile("cp.async.cg.shared.global [%0], [%1], 16;" :: "r"(saddr), "l"(gaddr));
}
__device__ __forceinline__ void cp_async8(unsigned saddr, const void* gaddr) {
    asm volatile("cp.async.ca.shared.global [%0], [%1], 8;" :: "r"(saddr), "l"(gaddr));
}
__device__ __forceinline__ void cp_commit() {
    asm volatile("cp.async.commit_group;" ::: "memory");
}
template<int NWAIT>
__device__ __forceinline__ void cp_wait() {
    asm volatile("cp.async.wait_group %0;" :: "n"(NWAIT) : "memory");
}

// ---- tf32 helpers ------------------------------------------------------
__device__ __forceinline__ unsigned f2tf32(float f) {
    unsigned r;
    asm("cvt.rna.tf32.f32 %0, %1;" : "=r"(r) : "f"(f));
    return r;
}
__device__ __forceinline__ void mma_tf32(float& c0, float& c1, float& c2, float& c3,
                                         unsigned a0, unsigned a1, unsigned a2, unsigned a3,
                                         unsigned b0, unsigned b1) {
    asm volatile(
        "mma.sync.aligned.m16n8k8.row.col.f32.tf32.tf32.f32 "
        "{%0,%1,%2,%3}, {%4,%5,%6,%7}, {%8,%9}, {%0,%1,%2,%3};"
        : "+f"(c0), "+f"(c1), "+f"(c2), "+f"(c3)
        : "r"(a0), "r"(a1), "r"(a2), "r"(a3), "r"(b0), "r"(b1));
}

// ---- log1p(t), t in [0,1]: degree-7 poly (err ~2e-7), MUFU-free ---------
__device__ __forceinline__ float log1p_poly(float t) {
    const float u = fmaf(2.f, t, -1.f);
    float p = 0.0000800429f;
    p = fmaf(p, u, -0.000272121f);
    p = fmaf(p, u,  0.000811464f);
    p = fmaf(p, u, -0.00305802f);
    p = fmaf(p, u,  0.01234897f);
    p = fmaf(p, u, -0.05556137f);
    p = fmaf(p, u,  0.33333319f);
    p = fmaf(p, u,  0.4054653f);
    return p;
}

// ---------------------------------------------------------------------------
// wfold + zero histogram counters
// ---------------------------------------------------------------------------
__global__ void wfold_kernel(const float* __restrict__ W2s, const float* __restrict__ Wsc_s,
                             const float* __restrict__ W2v, const float* __restrict__ Wsc_v)
{
    const int i = blockIdx.x * blockDim.x + threadIdx.x;
    if (i < N_NODES) d_cnt[i] = 0;
    if (i >= 40960) return;
    const int n = i / 640, k = i - n * 640;
    const float vs = (k < 128) ? W2s[k * 64 + n] * SC_A_C : Wsc_s[(k - 128) * 64 + n] * SC_B_C;
    const float vv = (k < 128) ? W2v[k * 64 + n] * SC_A_C : Wsc_v[(k - 128) * 64 + n] * SC_B_C;
    d_WcatT_s[i] = __uint_as_float(f2tf32(vs));
    d_WcatT_v[i] = __uint_as_float(f2tf32(vv));
}

// ---------------------------------------------------------------------------
// counting sort by dst: hist -> scan -> scatter
// ---------------------------------------------------------------------------
__global__ void hist_kernel(const int* __restrict__ edge_idx) {
    const int e = blockIdx.x * blockDim.x + threadIdx.x;
    if (e < N_EDGES) atomicAdd(&d_cnt[edge_idx[2 * e]], 1);
}

__global__ void __launch_bounds__(256) scan_kernel() {
    __shared__ int part[256];
    const int tid = threadIdx.x;
    const int CH = (N_NODES + 255) / 256;   // 79
    const int base = tid * CH;
    int s = 0;
    for (int j = 0; j < CH; ++j) {
        const int idx = base + j;
        if (idx < N_NODES) s += d_cnt[idx];
    }
    part[tid] = s;
    __syncthreads();
    if (tid == 0) {
        int run = 0;
        for (int i = 0; i < 256; ++i) { const int t = part[i]; part[i] = run; run += t; }
    }
    __syncthreads();
    int run = part[tid];
    for (int j = 0; j < CH; ++j) {
        const int idx = base + j;
        if (idx < N_NODES) { d_ofs[idx] = run; run += d_cnt[idx]; }
    }
}

__global__ void scatter_kernel(const int* __restrict__ edge_idx) {
    const int e = blockIdx.x * blockDim.x + threadIdx.x;
    if (e < N_EDGES) {
        const int dst = edge_idx[2 * e];
        const int pos = atomicAdd(&d_ofs[dst], 1);
        d_perm[pos] = e;
    }
}

// ---------------------------------------------------------------------------
// node prep (unchanged)
// ---------------------------------------------------------------------------
__global__ void __launch_bounds__(256)
nodeprep_kernel(const float* __restrict__ node_feat,
                const float* __restrict__ node_attr,
                const float* __restrict__ W1s,
                const float* __restrict__ W1v)
{
    __shared__ float sW1s[4096];
    __shared__ float sW1v[4096];
    __shared__ float sNF[4][256];
    __shared__ float4 sAT[4][2];

    const int tid = threadIdx.x;
    for (int i = tid; i < 4096; i += 256) { sW1s[i] = W1s[i]; sW1v[i] = W1v[i]; }
    __syncthreads();

    const int ngroups = N_NODES / 4;
    for (int g = blockIdx.x; g < ngroups; g += gridDim.x) {
        const int n0 = g * 4;
        __syncthreads();
        for (int i = tid; i < 1024; i += 256) {
            const int nl = i >> 8, j = i & 255;
            sNF[nl][j] = node_feat[(size_t)(n0 + nl) * 256 + j];
        }
        if (tid < 8) {
            const int nl = tid >> 1, j = tid & 1;
            sAT[nl][j] = __ldg(reinterpret_cast<const float4*>(node_attr + (size_t)(n0 + nl) * 8) + j);
        }
        __syncthreads();

        {
            const int nl = tid >> 6, w = tid & 63;
            const int n = n0 + nl;
            float sacc = 0.f, v0a = 0.f, v1a = 0.f, v2a = 0.f;
#pragma unroll
            for (int u = 0; u < 64; ++u) {
                const float ws = sW1s[u * 64 + w];
                const float wvv = sW1v[u * 64 + w];
                sacc = fmaf(sNF[nl][u], ws, sacc);
                v0a  = fmaf(sNF[nl][64 + 3 * u + 0], wvv, v0a);
                v1a  = fmaf(sNF[nl][64 + 3 * u + 1], wvv, v1a);
                v2a  = fmaf(sNF[nl][64 + 3 * u + 2], wvv, v2a);
            }
            float* o = d_sv + (size_t)n * 256;
            o[w] = sacc * INV_MUL_C;
            o[64 + 3 * w + 0] = v0a * INV_MUL_C;
            o[64 + 3 * w + 1] = v1a * INV_MUL_C;
            o[64 + 3 * w + 2] = v2a * INV_MUL_C;
        }

        if (tid < 128) {
            const int nl = tid >> 5, u = tid & 31;
            reinterpret_cast<float4*>(d_cat_s + (size_t)(n0 + nl) * 640)[u] =
                make_float4(0.f, 0.f, 0.f, 0.f);
        }
        for (int i = tid; i < 384; i += 256) {
            const int rr = i >> 5, u = i & 31;
            const int nl = rr / 3, c = rr - 3 * nl;
            reinterpret_cast<float4*>(d_cat_v + ((size_t)(n0 + nl) * 3 + c) * 640)[u] =
                make_float4(0.f, 0.f, 0.f, 0.f);
        }

        for (int i = tid; i < 512; i += 256) {
            const int nl = i >> 7, p4 = i & 127;
            const float a = sNF[nl][p4 >> 1];
            const float4 at = sAT[nl][p4 & 1];
            reinterpret_cast<float4*>(d_cat_s + (size_t)(n0 + nl) * 640 + 128)[p4] =
                make_float4(a * at.x, a * at.y, a * at.z, a * at.w);
        }
        for (int i = tid; i < 1536; i += 256) {
            const int nl = i / 384;
            const int r  = i - nl * 384;
            const int c  = r >> 7, p4 = r & 127;
            const float a = sNF[nl][64 + 3 * (p4 >> 1) + c];
            const float4 at = sAT[nl][p4 & 1];
            reinterpret_cast<float4*>(d_cat_v + ((size_t)(n0 + nl) * 3 + c) * 640 + 128)[p4] =
                make_float4(a * at.x, a * at.y, a * at.z, a * at.w);
        }
    }
}

// ---------------------------------------------------------------------------
// edge kernel v6: dst-sorted tiles via d_perm, segmented in-smem aggregation,
// cp.reduce only per segment (avg ~2/tile instead of 16).
// smem (floats):
//   sOut [0,16512)      2*16*516
//   sGat [16512,24832)  2*16*260
//   sH   [24832,25920)  16*68
//   sWfc1[25920,26432)
//   sBas [26432,26688)  2*16*8
//   sShs [26688,26816)  2*16*4
//   sIdx [26816,26880)  2*16*2 ints
//   sPerm[26880,26912)  2*16 ints
//   sStart[26912,26928) 16 ints
// total 26928 floats = 107712 B -> 2 CTAs/SM
// ---------------------------------------------------------------------------
#define SOUT_STRIDE 516
#define GAT_STRIDE 260
#define EDGE_SMEM (26928 * 4)

__global__ void __launch_bounds__(256, 2)
edge_kernel(const float* __restrict__ edge_sh,
            const float* __restrict__ edge_basis,
            const float* __restrict__ Wfc1,
            const float* __restrict__ Wfc2,
            const int*   __restrict__ edge_idx)
{
    extern __shared__ float esm[];
    float*    sOut  = esm;
    float*    sGat  = esm + 16512;
    float*    sH    = esm + 24832;
    unsigned* sHu   = reinterpret_cast<unsigned*>(sH);
    float*    sWfc1 = esm + 25920;
    float*    sBas  = esm + 26432;
    float*    sShs  = esm + 26688;
    int*      sIdx  = (int*)(esm + 26816);
    int*      sPerm = (int*)(esm + 26880);
    int*      sStart= (int*)(esm + 26912);

    const int tid  = threadIdx.x;
    const int lane = tid & 31, warp = tid >> 5;
    const int g    = lane >> 2;
    const int ctig = lane & 3;
    const int n0   = warp * 32;
    const int region = warp >> 1;

    unsigned bfrag[8][4][2];
#pragma unroll
    for (int ks = 0; ks < 8; ++ks)
#pragma unroll
        for (int nb = 0; nb < 4; ++nb) {
            const int nn = n0 + nb * 8 + g;
            bfrag[ks][nb][0] = f2tf32(Wfc2[(ks * 8 + ctig    ) * 256 + nn] * W_SCALE);
            bfrag[ks][nb][1] = f2tf32(Wfc2[(ks * 8 + ctig + 4) * 256 + nn] * W_SCALE);
        }
    for (int i = tid; i < 512; i += 256) sWfc1[i] = Wfc1[i] * INV_SQRT8_C;

    const int niter = N_EDGES / EPB;   // 20000

    // scattered edge-row bundle for tile it_tgt (edges via sPerm[ebuf]),
    // plus contiguous perm prefetch for tile it_perm into sPerm[pbuf].
    auto bundle_issue = [&](int ebuf, int it_tgt, int pbuf, int it_perm) {
        if (tid < 64) {
            if (it_tgt < niter) {
                const int q = tid >> 2, part = tid & 3;
                const int e = sPerm[ebuf * 16 + q];
                if (part == 0)
                    cp_async16(smem_u32(sBas + ebuf * 128 + q * 8), edge_basis + (size_t)e * 8);
                else if (part == 1)
                    cp_async16(smem_u32(sBas + ebuf * 128 + q * 8 + 4), edge_basis + (size_t)e * 8 + 4);
                else if (part == 2)
                    cp_async16(smem_u32(sShs + ebuf * 64 + q * 4), edge_sh + (size_t)e * 4);
                else
                    cp_async8(smem_u32(sIdx + ebuf * 32 + q * 2), edge_idx + (size_t)e * 2);
            }
        } else if (tid < 68) {
            if (it_perm < niter) {
                const int j = tid - 64;
                cp_async16(smem_u32(sPerm + pbuf * 16 + j * 4),
                           d_perm + (size_t)it_perm * 16 + j * 4);
            }
        }
    };

    auto gather_issue = [&](int gbuf, int ibuf, bool valid) {
        if (valid) {
#pragma unroll
            for (int j = 0; j < 4; ++j) {
                const int c = tid + 256 * j;
                const int row = c >> 6;
                const int off = (c & 63) * 4;
                const int src = sIdx[ibuf * 32 + 2 * row + 1];
                cp_async16(smem_u32(sGat + (gbuf * 16 + row) * GAT_STRIDE + off),
                           d_sv + (size_t)src * 256 + off);
            }
        }
    };

    // prologue
    if (tid < 16) sPerm[tid] = d_perm[(size_t)blockIdx.x * 16 + tid];
    __syncthreads();
    bundle_issue(0, blockIdx.x, 1, blockIdx.x + gridDim.x);
    cp_commit();
    cp_wait<0>();
    __syncthreads();
    gather_issue(0, 0, true);
    cp_commit();                        // pending: [gather(it0)]

    int li = 0;
    for (int it = blockIdx.x; it < niter; it += gridDim.x, ++li) {
        const int cur = li & 1;
        const int nit  = it + gridDim.x;
        const int nit2 = it + 2 * gridDim.x;

        if (tid < 64) asm volatile("cp.async.bulk.wait_group 1;" ::: "memory");

        bundle_issue(cur ^ 1, nit, cur, nit2);
        cp_commit();                    // pending: [gather(it), bundle(it+1)]

        // phase A
#pragma unroll
        for (int i = tid; i < EPB * 64; i += 256) {
            const int el = i >> 6, k = i & 63;
            const float* bb = sBas + cur * 128 + el * 8;
            const float4 b0 = ld4s(bb);
            const float4 b1 = ld4s(bb + 4);
            float acc;
            acc = b0.x * sWfc1[0 * 64 + k];
            acc = fmaf(b0.y, sWfc1[1 * 64 + k], acc);
            acc = fmaf(b0.z, sWfc1[2 * 64 + k], acc);
            acc = fmaf(b0.w, sWfc1[3 * 64 + k], acc);
            acc = fmaf(b1.x, sWfc1[4 * 64 + k], acc);
            acc = fmaf(b1.y, sWfc1[5 * 64 + k], acc);
            acc = fmaf(b1.z, sWfc1[6 * 64 + k], acc);
            acc = fmaf(b1.w, sWfc1[7 * 64 + k], acc);
            const float t = __expf(-fabsf(acc));
            const float h = fmaxf(acc, 0.f) + log1p_poly(t) - LOG2_C;
            sHu[el * 68 + k] = f2tf32(h);
        }

        cp_wait<1>();                   // gather(it) landed
        __syncthreads();

        // phase B
        float acc[4][4];
#pragma unroll
        for (int nb = 0; nb < 4; ++nb)
#pragma unroll
            for (int j = 0; j < 4; ++j) acc[nb][j] = 0.f;
#pragma unroll
        for (int ks = 0; ks < 8; ++ks) {
            const unsigned a0 = sHu[ g      * 68 + ks * 8 + ctig    ];
            const unsigned a1 = sHu[(g + 8) * 68 + ks * 8 + ctig    ];
            const unsigned a2 = sHu[ g      * 68 + ks * 8 + ctig + 4];
            const unsigned a3 = sHu[(g + 8) * 68 + ks * 8 + ctig + 4];
#pragma unroll
            for (int nb = 0; nb < 4; ++nb)
                mma_tf32(acc[nb][0], acc[nb][1], acc[nb][2], acc[nb][3],
                         a0, a1, a2, a3, bfrag[ks][nb][0], bfrag[ks][nb][1]);
        }

        // segment starts (dst-sorted tile)
        if (tid < 16)
            sStart[tid] = (tid == 0) ||
                          (sIdx[cur * 32 + 2 * tid] != sIdx[cur * 32 + 2 * (tid - 1)]);

        // phase C
        auto process = [&](float w, int q, int col) {
            const float* nrow = sGat + (cur * 16 + q) * GAT_STRIDE;
            const float4 sh = *reinterpret_cast<const float4*>(sShs + cur * 64 + 4 * q);
            float* st = sOut + (cur * EPB + q) * SOUT_STRIDE;
            if (region == 0) {
                st[col] = w * nrow[col] * sh.x;
            } else if (region == 1) {
                const int u = col - 64;
                const float b = w * nrow[u];
                st[128 + u] = b * sh.y;
                st[256 + u] = b * sh.z;
                st[384 + u] = b * sh.w;
            } else if (region == 2) {
                const int u = col - 128;
                const float ws = w * sh.x;
                st[128 + 64 + u] = ws * nrow[64 + 3 * u + 0];
                st[256 + 64 + u] = ws * nrow[64 + 3 * u + 1];
                st[384 + 64 + u] = ws * nrow[64 + 3 * u + 2];
            } else {
                const int u = col - 192;
                const float x0 = nrow[64 + 3 * u + 0];
                const float x1 = nrow[64 + 3 * u + 1];
                const float x2 = nrow[64 + 3 * u + 2];
                st[64 + u] = w * INV_SQRT3_C * (x0 * sh.y + x1 * sh.z + x2 * sh.w);
            }
        };
#pragma unroll
        for (int nb = 0; nb < 4; ++nb) {
            const int colb = n0 + nb * 8 + 2 * ctig;
            process(acc[nb][0], g,     colb);
            process(acc[nb][1], g,     colb + 1);
            process(acc[nb][2], g + 8, colb);
            process(acc[nb][3], g + 8, colb + 1);
        }

        cp_wait<0>();                   // bundle(it+1) (and perm it+2) landed
        __syncthreads();

        // segmented in-place aggregation over equal-dst runs
        {
            const int c = 2 * tid;      // cols c, c+1 of 512
            float2 accv = make_float2(0.f, 0.f);
            int qs = 0;
#pragma unroll
            for (int q = 0; q < 16; ++q) {
                if (q > 0 && sStart[q]) {
                    *reinterpret_cast<float2*>(sOut + (cur * EPB + qs) * SOUT_STRIDE + c) = accv;
                    accv = make_float2(0.f, 0.f);
                    qs = q;
                }
                const float2 v = *reinterpret_cast<const float2*>(
                    sOut + (cur * EPB + q) * SOUT_STRIDE + c);
                accv.x += v.x; accv.y += v.y;
            }
            *reinterpret_cast<float2*>(sOut + (cur * EPB + qs) * SOUT_STRIDE + c) = accv;
        }
        __syncthreads();

        // bulk reduces: one per segment-start slot
        if (tid < 64) {
            asm volatile("fence.proxy.async.shared::cta;" ::: "memory");
            const int q = tid >> 2, part = tid & 3;
            if (sStart[q]) {
                const int dst = sIdx[cur * 32 + 2 * q];
                float* gp = (part == 0)
                          ? (d_cat_s + (size_t)dst * 640)
                          : (d_cat_v + ((size_t)dst * 3 + (part - 1)) * 640);
                const unsigned saddr = smem_u32(sOut + (cur * EPB + q) * SOUT_STRIDE + part * 128);
                asm volatile(
                    "cp.reduce.async.bulk.global.shared::cta.bulk_group.add.f32 [%0], [%1], %2;"
                    :: "l"(gp), "r"(saddr), "n"(512) : "memory");
            }
            asm volatile("cp.async.bulk.commit_group;" ::: "memory");
        }

        // gather for next iteration
        gather_issue(cur ^ 1, cur ^ 1, nit < niter);
        cp_commit();                    // pending: [gather(it+1)]
    }
    if (tid < 64) asm volatile("cp.async.bulk.wait_group 0;" ::: "memory");
}

// ===========================================================================
// Unified tf32 tensor-core out-GEMM (unchanged)
// ===========================================================================
#define KCH 80
#define PAD 84
#define GEMM_SMEM (4 * 64 * PAD * 4)

__global__ void __launch_bounds__(256, 2)
out_gemm_tc(float* __restrict__ out)
{
    const int bid  = blockIdx.x;
    const int mode = (bid >= TILES_S);
    const int tile = mode ? bid - TILES_S : bid;
    const float* __restrict__ A  = mode ? d_cat_v   : d_cat_s;
    const float* __restrict__ Bt = mode ? d_WcatT_v : d_WcatT_s;

    extern __shared__ float sm[];
    float* sA = sm;
    float* sB = sm + 2 * 64 * PAD;

    const int tid = threadIdx.x;
    const int lane = tid & 31, warp = tid >> 5;
    const int g = lane >> 2, ctig = lane & 3;
    const int m0 = (warp & 3) * 16;
    const int n0 = (warp >> 2) * 32;
    const int r0 = tile * 64;

    auto stage = [&](int buf, int c) {
        const int k0 = c * KCH;
        float* sAb = sA + buf * 64 * PAD;
        float* sBb = sB + buf * 64 * PAD;
#pragma unroll
        for (int j = 0; j < 5; ++j) {
            const int idx = tid + 256 * j;
            const int row = idx / 20, u = idx - row * 20;
            cp_async16(smem_u32(sAb + row * PAD + 4 * u),
                       A + (size_t)(r0 + row) * 640 + k0 + 4 * u);
            cp_async16(smem_u32(sBb + row * PAD + 4 * u),
                       Bt + (size_t)row * 640 + k0 + 4 * u);
        }
        cp_commit();
    };

    float acc[4][4];
#pragma unroll
    for (int nb = 0; nb < 4; ++nb)
#pragma unroll
        for (int j = 0; j < 4; ++j) acc[nb][j] = 0.f;

    stage(0, 0);

#pragma unroll 1
    for (int c = 0; c < 8; ++c) {
        if (c < 7) { stage((c + 1) & 1, c + 1); cp_wait<1>(); }
        else       { cp_wait<0>(); }
        __syncthreads();

        const float* pa = sA + (c & 1) * 64 * PAD + m0 * PAD;
        const float* pb = sB + (c & 1) * 64 * PAD + n0 * PAD;
#pragma unroll
        for (int ks = 0; ks < KCH / 8; ++ks) {
            const int kb = ks * 8;
            const unsigned a0 = f2tf32(pa[ g      * PAD + kb + ctig    ]);
            const unsigned a1 = f2tf32(pa[(g + 8) * PAD + kb + ctig    ]);
            const unsigned a2 = f2tf32(pa[ g      * PAD + kb + ctig + 4]);
            const unsigned a3 = f2tf32(pa[(g + 8) * PAD + kb + ctig + 4]);
#pragma unroll
            for (int nb = 0; nb < 4; ++nb) {
                const unsigned b0 = __float_as_uint(pb[(nb * 8 + g) * PAD + kb + ctig    ]);
                const unsigned b1 = __float_as_uint(pb[(nb * 8 + g) * PAD + kb + ctig + 4]);
                mma_tf32(acc[nb][0], acc[nb][1], acc[nb][2], acc[nb][3],
                         a0, a1, a2, a3, b0, b1);
            }
        }
        __syncthreads();
    }

#pragma unroll
    for (int nb = 0; nb < 4; ++nb) {
        const int col = n0 + nb * 8 + 2 * ctig;
        const int row1 = r0 + m0 + g;
        const int row2 = row1 + 8;
        if (mode == 0) {
            if (row1 < N_NODES)
                *reinterpret_cast<float2*>(out + (size_t)row1 * 256 + col) =
                    make_float2(acc[nb][0], acc[nb][1]);
            if (row2 < N_NODES)
                *reinterpret_cast<float2*>(out + (size_t)row2 * 256 + col) =
                    make_float2(acc[nb][2], acc[nb][3]);
        } else {
            if (row1 < 3 * N_NODES) {
                const int n = row1 / 3, cc = row1 - 3 * (row1 / 3);
                float* o = out + (size_t)n * 256 + 64 + cc;
                o[3 * col] = acc[nb][0];
                o[3 * (col + 1)] = acc[nb][1];
            }
            if (row2 < 3 * N_NODES) {
                const int n = row2 / 3, cc = row2 - 3 * (row2 / 3);
                float* o = out + (size_t)n * 256 + 64 + cc;
                o[3 * col] = acc[nb][2];
                o[3 * (col + 1)] = acc[nb][3];
            }
        }
    }
}

// ---------------------------------------------------------------------------
extern "C" void kernel_launch(void* const* d_in, const int* /*in_sizes*/, int /*n_in*/,
                              void* d_out, int /*out_size*/)
{
    const float* node_feat  = (const float*)d_in[0];
    const float* node_attr  = (const float*)d_in[1];
    const float* edge_sh    = (const float*)d_in[2];
    const float* edge_basis = (const float*)d_in[3];
    const float* W1s        = (const float*)d_in[4];
    const float* W1v        = (const float*)d_in[5];
    const float* Wfc1       = (const float*)d_in[6];
    const float* Wfc2       = (const float*)d_in[7];
    const float* W2s        = (const float*)d_in[8];
    const float* W2v        = (const float*)d_in[9];
    const float* Wsc_s      = (const float*)d_in[10];
    const float* Wsc_v      = (const float*)d_in[11];
    const int*   edge_idx   = (const int*)d_in[12];
    float* out = (float*)d_out;

    cudaFuncSetAttribute(edge_kernel, cudaFuncAttributeMaxDynamicSharedMemorySize, EDGE_SMEM);
    cudaFuncSetAttribute(out_gemm_tc, cudaFuncAttributeMaxDynamicSharedMemorySize, GEMM_SMEM);

    wfold_kernel<<<160, 256>>>(W2s, Wsc_s, W2v, Wsc_v);
    hist_kernel<<<(N_EDGES + 255) / 256, 256>>>(edge_idx);
    scan_kernel<<<1, 256>>>();
    scatter_kernel<<<(N_EDGES + 255) / 256, 256>>>(edge_idx);
    nodeprep_kernel<<<296, 256>>>(node_feat, node_attr, W1s, W1v);
    edge_kernel<<<296, 256, EDGE_SMEM>>>(edge_sh, edge_basis, Wfc1, Wfc2, edge_idx);

    out_gemm_tc<<<TILES_S + TILES_V, 256, GEMM_SMEM>>>(out);
}